// round 1
// baseline (speedup 1.0000x reference)
#include <cuda_runtime.h>

#define NN   100000
#define EE   1600000
#define DIMD 64
#define FOUT 2
#define BN_EPS 1e-5f

// ---------------- scratch (static __device__ globals; no allocs) ----------------
__device__ float g_agg1[(size_t)NN * DIMD];
__device__ float g_h1  [(size_t)NN * DIMD];
__device__ float g_bn1 [(size_t)NN * DIMD];
__device__ float g_agg2[(size_t)NN * DIMD];
__device__ float g_h2  [(size_t)NN * FOUT];

__device__ float g_sum1[DIMD], g_sq1[DIMD];
__device__ float g_sum2[FOUT], g_sq2[FOUT];
__device__ float g_a1[DIMD], g_c1[DIMD];
__device__ float g_a2[FOUT], g_c2[FOUT];
__device__ int   g_is64;

// ---------------- init: zero stats + detect index dtype ----------------
__global__ void k_init(const unsigned long long* idx) {
    int t = threadIdx.x;
    if (t < DIMD) { g_sum1[t] = 0.f; g_sq1[t] = 0.f; }
    if (t < FOUT) { g_sum2[t] = 0.f; g_sq2[t] = 0.f; }
    if (t == 0) {
        // int64 indices: every u64 word < 100000. int32 data reinterpreted as
        // u64 has a (generally nonzero) index in the high word -> huge value.
        int is64 = 1;
        for (int i = 0; i < 64; i++)
            if (idx[i] >= 100000ULL) { is64 = 0; break; }
        g_is64 = is64;
    }
}

// ---------------- copy x -> agg1 (identity term of GIN) ----------------
__global__ void k_copy(const float4* __restrict__ src, float4* __restrict__ dst, int n4) {
    int i = blockIdx.x * blockDim.x + threadIdx.x;
    if (i < n4) dst[i] = src[i];
}

// ---------------- edge scatter: agg[dst] += feat[src], float4 atomics ----------------
// grid = EE*16/256 blocks exactly; 16 threads (16 float4) per edge.
__global__ void k_scatter(const void* __restrict__ idxbuf,
                          const float4* __restrict__ feat,
                          float4* __restrict__ agg) {
    int g = blockIdx.x * 256 + threadIdx.x;
    int e = g >> 4;
    int f = g & 15;
    int s, d;
    if (g_is64) {
        const long long* p = (const long long*)idxbuf;
        s = (int)p[e]; d = (int)p[(size_t)EE + e];
    } else {
        const int* p = (const int*)idxbuf;
        s = p[e]; d = p[EE + e];
    }
    float4 v = feat[(size_t)s * 16 + f];
    atomicAdd(&agg[(size_t)d * 16 + f], v);
}

// ---------------- MLP 64 -> 64 -> 64, ReLUs, one row per thread ----------------
// dynamic smem: sWa(4096) | sWb(4096) | sBa(64) | sBb(64) | hidS(blockDim*65)
__global__ void k_mlp64(const float* __restrict__ Wa, const float* __restrict__ ba,
                        const float* __restrict__ Wb, const float* __restrict__ bb,
                        const float* __restrict__ in, float* __restrict__ out) {
    extern __shared__ float sm[];
    float* sWa  = sm;             // transposed [j][k]
    float* sWb  = sm + 4096;      // transposed [j][k]
    float* sBa  = sm + 8192;
    float* sBb  = sm + 8256;
    float* hidS = sm + 8320;      // [blockDim][65]

    int tid = threadIdx.x;
    for (int i = tid; i < 4096; i += blockDim.x) {
        int j = i >> 6, k = i & 63;
        sWa[i] = Wa[k * 64 + j];
        sWb[i] = Wb[k * 64 + j];
    }
    if (tid < 64) { sBa[tid] = ba[tid]; sBb[tid] = bb[tid]; }
    __syncthreads();

    int r = blockIdx.x * blockDim.x + tid;
    if (r >= NN) return;

    float xin[64];
    const float4* row = (const float4*)in + (size_t)r * 16;
    #pragma unroll
    for (int k4 = 0; k4 < 16; k4++) {
        float4 v = row[k4];
        xin[4*k4] = v.x; xin[4*k4+1] = v.y; xin[4*k4+2] = v.z; xin[4*k4+3] = v.w;
    }

    float* myHid = hidS + tid * 65;
    #pragma unroll 1
    for (int j = 0; j < 64; j++) {
        const float4* w = (const float4*)(sWa + j * 64);
        float a0 = sBa[j], a1 = 0.f, a2 = 0.f, a3 = 0.f;
        #pragma unroll
        for (int k4 = 0; k4 < 16; k4 += 4) {
            float4 w0 = w[k4+0], w1 = w[k4+1], w2 = w[k4+2], w3 = w[k4+3];
            a0 = fmaf(xin[4*k4+0],  w0.x, a0); a0 = fmaf(xin[4*k4+1],  w0.y, a0);
            a0 = fmaf(xin[4*k4+2],  w0.z, a0); a0 = fmaf(xin[4*k4+3],  w0.w, a0);
            a1 = fmaf(xin[4*k4+4],  w1.x, a1); a1 = fmaf(xin[4*k4+5],  w1.y, a1);
            a1 = fmaf(xin[4*k4+6],  w1.z, a1); a1 = fmaf(xin[4*k4+7],  w1.w, a1);
            a2 = fmaf(xin[4*k4+8],  w2.x, a2); a2 = fmaf(xin[4*k4+9],  w2.y, a2);
            a2 = fmaf(xin[4*k4+10], w2.z, a2); a2 = fmaf(xin[4*k4+11], w2.w, a2);
            a3 = fmaf(xin[4*k4+12], w3.x, a3); a3 = fmaf(xin[4*k4+13], w3.y, a3);
            a3 = fmaf(xin[4*k4+14], w3.z, a3); a3 = fmaf(xin[4*k4+15], w3.w, a3);
        }
        myHid[j] = fmaxf((a0 + a1) + (a2 + a3), 0.f);
    }

    float h[64];
    #pragma unroll
    for (int k = 0; k < 64; k++) h[k] = myHid[k];

    float4* orow = (float4*)out + (size_t)r * 16;
    #pragma unroll 1
    for (int j4 = 0; j4 < 16; j4++) {
        float o[4];
        #pragma unroll
        for (int jj = 0; jj < 4; jj++) {
            int j = j4 * 4 + jj;
            const float4* w = (const float4*)(sWb + j * 64);
            float a0 = sBb[j], a1 = 0.f, a2 = 0.f, a3 = 0.f;
            #pragma unroll
            for (int k4 = 0; k4 < 16; k4 += 4) {
                float4 w0 = w[k4+0], w1 = w[k4+1], w2 = w[k4+2], w3 = w[k4+3];
                a0 = fmaf(h[4*k4+0],  w0.x, a0); a0 = fmaf(h[4*k4+1],  w0.y, a0);
                a0 = fmaf(h[4*k4+2],  w0.z, a0); a0 = fmaf(h[4*k4+3],  w0.w, a0);
                a1 = fmaf(h[4*k4+4],  w1.x, a1); a1 = fmaf(h[4*k4+5],  w1.y, a1);
                a1 = fmaf(h[4*k4+6],  w1.z, a1); a1 = fmaf(h[4*k4+7],  w1.w, a1);
                a2 = fmaf(h[4*k4+8],  w2.x, a2); a2 = fmaf(h[4*k4+9],  w2.y, a2);
                a2 = fmaf(h[4*k4+10], w2.z, a2); a2 = fmaf(h[4*k4+11], w2.w, a2);
                a3 = fmaf(h[4*k4+12], w3.x, a3); a3 = fmaf(h[4*k4+13], w3.y, a3);
                a3 = fmaf(h[4*k4+14], w3.z, a3); a3 = fmaf(h[4*k4+15], w3.w, a3);
            }
            o[jj] = fmaxf((a0 + a1) + (a2 + a3), 0.f);
        }
        orow[j4] = make_float4(o[0], o[1], o[2], o[3]);
    }
}

// ---------------- MLP 64 -> 64 -> 2, ReLUs ----------------
// dynamic smem: sWa(4096) | sBa(64) | sWb(128) | sBb(2+pad to 16) | hidS(blockDim*65)
__global__ void k_mlp2(const float* __restrict__ Wa, const float* __restrict__ ba,
                       const float* __restrict__ Wb, const float* __restrict__ bb,
                       const float* __restrict__ in, float* __restrict__ out) {
    extern __shared__ float sm[];
    float* sWa  = sm;             // transposed [j][k]
    float* sBa  = sm + 4096;
    float* sWb  = sm + 4160;      // transposed [j][k], 2x64
    float* sBb  = sm + 4288;
    float* hidS = sm + 4352;

    int tid = threadIdx.x;
    for (int i = tid; i < 4096; i += blockDim.x) {
        int j = i >> 6, k = i & 63;
        sWa[i] = Wa[k * 64 + j];
    }
    if (tid < 128) { int j = tid >> 6, k = tid & 63; sWb[j * 64 + k] = Wb[k * 2 + j]; }
    if (tid < 64)  sBa[tid] = ba[tid];
    if (tid < 2)   sBb[tid] = bb[tid];
    __syncthreads();

    int r = blockIdx.x * blockDim.x + tid;
    if (r >= NN) return;

    float xin[64];
    const float4* row = (const float4*)in + (size_t)r * 16;
    #pragma unroll
    for (int k4 = 0; k4 < 16; k4++) {
        float4 v = row[k4];
        xin[4*k4] = v.x; xin[4*k4+1] = v.y; xin[4*k4+2] = v.z; xin[4*k4+3] = v.w;
    }

    float* myHid = hidS + tid * 65;
    #pragma unroll 1
    for (int j = 0; j < 64; j++) {
        const float4* w = (const float4*)(sWa + j * 64);
        float a0 = sBa[j], a1 = 0.f, a2 = 0.f, a3 = 0.f;
        #pragma unroll
        for (int k4 = 0; k4 < 16; k4 += 4) {
            float4 w0 = w[k4+0], w1 = w[k4+1], w2 = w[k4+2], w3 = w[k4+3];
            a0 = fmaf(xin[4*k4+0],  w0.x, a0); a0 = fmaf(xin[4*k4+1],  w0.y, a0);
            a0 = fmaf(xin[4*k4+2],  w0.z, a0); a0 = fmaf(xin[4*k4+3],  w0.w, a0);
            a1 = fmaf(xin[4*k4+4],  w1.x, a1); a1 = fmaf(xin[4*k4+5],  w1.y, a1);
            a1 = fmaf(xin[4*k4+6],  w1.z, a1); a1 = fmaf(xin[4*k4+7],  w1.w, a1);
            a2 = fmaf(xin[4*k4+8],  w2.x, a2); a2 = fmaf(xin[4*k4+9],  w2.y, a2);
            a2 = fmaf(xin[4*k4+10], w2.z, a2); a2 = fmaf(xin[4*k4+11], w2.w, a2);
            a3 = fmaf(xin[4*k4+12], w3.x, a3); a3 = fmaf(xin[4*k4+13], w3.y, a3);
            a3 = fmaf(xin[4*k4+14], w3.z, a3); a3 = fmaf(xin[4*k4+15], w3.w, a3);
        }
        myHid[j] = fmaxf((a0 + a1) + (a2 + a3), 0.f);
    }

    float h[64];
    #pragma unroll
    for (int k = 0; k < 64; k++) h[k] = myHid[k];

    float o0 = sBb[0], o1 = sBb[1];
    const float4* w0r = (const float4*)(sWb);
    const float4* w1r = (const float4*)(sWb + 64);
    #pragma unroll
    for (int k4 = 0; k4 < 16; k4++) {
        float4 w0 = w0r[k4], w1 = w1r[k4];
        o0 = fmaf(h[4*k4+0], w0.x, o0); o0 = fmaf(h[4*k4+1], w0.y, o0);
        o0 = fmaf(h[4*k4+2], w0.z, o0); o0 = fmaf(h[4*k4+3], w0.w, o0);
        o1 = fmaf(h[4*k4+0], w1.x, o1); o1 = fmaf(h[4*k4+1], w1.y, o1);
        o1 = fmaf(h[4*k4+2], w1.z, o1); o1 = fmaf(h[4*k4+3], w1.w, o1);
    }
    ((float2*)out)[r] = make_float2(fmaxf(o0, 0.f), fmaxf(o1, 0.f));
}

// ---------------- column stats: 64 features ----------------
__global__ void k_stats64(const float* __restrict__ h) {
    int tid = threadIdx.x;                       // 256
    size_t gid = (size_t)blockIdx.x * 256 + tid;
    size_t stride = (size_t)gridDim.x * 256;     // multiple of 64
    float s = 0.f, q = 0.f;
    for (size_t i = gid; i < (size_t)NN * 64; i += stride) {
        float v = h[i]; s += v; q += v * v;
    }
    __shared__ float ss[256], sq[256];
    ss[tid] = s; sq[tid] = q;
    __syncthreads();
    if (tid < 64) {
        float S = ss[tid] + ss[tid+64] + ss[tid+128] + ss[tid+192];
        float Q = sq[tid] + sq[tid+64] + sq[tid+128] + sq[tid+192];
        atomicAdd(&g_sum1[tid], S);
        atomicAdd(&g_sq1[tid],  Q);
    }
}

// ---------------- column stats: 2 features ----------------
__global__ void k_stats2(const float* __restrict__ h) {
    int tid = threadIdx.x;                       // 256
    size_t gid = (size_t)blockIdx.x * 256 + tid;
    size_t stride = (size_t)gridDim.x * 256;     // multiple of 2
    float s = 0.f, q = 0.f;
    for (size_t i = gid; i < (size_t)NN * 2; i += stride) {
        float v = h[i]; s += v; q += v * v;
    }
    __shared__ float ss[256], sq[256];
    ss[tid] = s; sq[tid] = q;
    __syncthreads();
    if (tid < 2) {
        float S = 0.f, Q = 0.f;
        for (int i = tid; i < 256; i += 2) { S += ss[i]; Q += sq[i]; }
        atomicAdd(&g_sum2[tid], S);
        atomicAdd(&g_sq2[tid],  Q);
    }
}

// ---------------- finalize BN affine: a = g*rsqrt(var+eps), c = be - mu*a ----------------
__global__ void k_finalize(const float* __restrict__ sum, const float* __restrict__ sq,
                           const float* __restrict__ g, const float* __restrict__ be,
                           float* __restrict__ a, float* __restrict__ c, int n) {
    int i = threadIdx.x;
    if (i < n) {
        float mu  = sum[i] * (1.f / NN);
        float var = sq[i] * (1.f / NN) - mu * mu;
        float rs  = rsqrtf(var + BN_EPS);
        float aa  = g[i] * rs;
        a[i] = aa;
        c[i] = be[i] - mu * aa;
    }
}

// ---------------- apply BN1 and seed agg2 ----------------
__global__ void k_apply1(const float4* __restrict__ h,
                         float4* __restrict__ bn, float4* __restrict__ agg) {
    __shared__ float sa[64], sc[64];
    if (threadIdx.x < 64) { sa[threadIdx.x] = g_a1[threadIdx.x]; sc[threadIdx.x] = g_c1[threadIdx.x]; }
    __syncthreads();
    int i = blockIdx.x * blockDim.x + threadIdx.x;
    if (i < NN * 16) {
        int f = (i & 15) * 4;
        float4 v = h[i];
        v.x = v.x * sa[f+0] + sc[f+0];
        v.y = v.y * sa[f+1] + sc[f+1];
        v.z = v.z * sa[f+2] + sc[f+2];
        v.w = v.w * sa[f+3] + sc[f+3];
        bn[i]  = v;
        agg[i] = v;
    }
}

// ---------------- apply BN2 -> d_out ----------------
__global__ void k_apply2(const float2* __restrict__ h, float2* __restrict__ out) {
    int i = blockIdx.x * blockDim.x + threadIdx.x;
    if (i < NN) {
        float a0 = g_a2[0], a1 = g_a2[1], c0 = g_c2[0], c1 = g_c2[1];
        float2 v = h[i];
        out[i] = make_float2(v.x * a0 + c0, v.y * a1 + c1);
    }
}

// ---------------- launch ----------------
extern "C" void kernel_launch(void* const* d_in, const int* in_sizes, int n_in,
                              void* d_out, int out_size) {
    const float* x    = (const float*)d_in[0];
    const void*  eidx = d_in[1];
    const float* W1a  = (const float*)d_in[2];
    const float* b1a  = (const float*)d_in[3];
    const float* W1b  = (const float*)d_in[4];
    const float* b1b  = (const float*)d_in[5];
    const float* g1   = (const float*)d_in[6];
    const float* be1  = (const float*)d_in[7];
    const float* W5a  = (const float*)d_in[8];
    const float* b5a  = (const float*)d_in[9];
    const float* W5b  = (const float*)d_in[10];
    const float* b5b  = (const float*)d_in[11];
    const float* g5   = (const float*)d_in[12];
    const float* be5  = (const float*)d_in[13];

    float *agg1, *h1, *bn1, *agg2, *h2;
    float *sum1, *sq1, *sum2, *sq2, *a1, *c1, *a2, *c2;
    cudaGetSymbolAddress((void**)&agg1, g_agg1);
    cudaGetSymbolAddress((void**)&h1,   g_h1);
    cudaGetSymbolAddress((void**)&bn1,  g_bn1);
    cudaGetSymbolAddress((void**)&agg2, g_agg2);
    cudaGetSymbolAddress((void**)&h2,   g_h2);
    cudaGetSymbolAddress((void**)&sum1, g_sum1);
    cudaGetSymbolAddress((void**)&sq1,  g_sq1);
    cudaGetSymbolAddress((void**)&sum2, g_sum2);
    cudaGetSymbolAddress((void**)&sq2,  g_sq2);
    cudaGetSymbolAddress((void**)&a1,   g_a1);
    cudaGetSymbolAddress((void**)&c1,   g_c1);
    cudaGetSymbolAddress((void**)&a2,   g_a2);
    cudaGetSymbolAddress((void**)&c2,   g_c2);

    const int smem_mlp64 = (8320 + 128 * 65) * 4;
    const int smem_mlp2  = (4352 + 128 * 65) * 4;
    cudaFuncSetAttribute(k_mlp64, cudaFuncAttributeMaxDynamicSharedMemorySize, smem_mlp64);
    cudaFuncSetAttribute(k_mlp2,  cudaFuncAttributeMaxDynamicSharedMemorySize, smem_mlp2);

    const int nb_copy    = (NN * 16 + 255) / 256;
    const int nb_scatter = (EE * 16) / 256;           // exact: 100000
    const int nb_mlp     = (NN + 127) / 128;
    const int nb_apply2  = (NN + 255) / 256;

    // layer 1
    k_init<<<1, 128>>>((const unsigned long long*)eidx);
    k_copy<<<nb_copy, 256>>>((const float4*)x, (float4*)agg1, NN * 16);
    k_scatter<<<nb_scatter, 256>>>(eidx, (const float4*)x, (float4*)agg1);
    k_mlp64<<<nb_mlp, 128, smem_mlp64>>>(W1a, b1a, W1b, b1b, agg1, h1);
    k_stats64<<<256, 256>>>(h1);
    k_finalize<<<1, 64>>>(sum1, sq1, g1, be1, a1, c1, DIMD);
    k_apply1<<<nb_copy, 256>>>((const float4*)h1, (float4*)bn1, (float4*)agg2);
    // layer 2
    k_scatter<<<nb_scatter, 256>>>(eidx, (const float4*)bn1, (float4*)agg2);
    k_mlp2<<<nb_mlp, 128, smem_mlp2>>>(W5a, b5a, W5b, b5b, agg2, h2);
    k_stats2<<<128, 256>>>(h2);
    k_finalize<<<1, 64>>>(sum2, sq2, g5, be5, a2, c2, FOUT);
    k_apply2<<<nb_apply2, 256>>>((const float2*)h2, (float2*)d_out);
}

// round 2
// speedup vs baseline: 1.1643x; 1.1643x over previous
#include <cuda_runtime.h>

#define NN   100000
#define EE   1600000
#define DIMD 64
#define FOUT 2
#define BN_EPS 1e-5f
#define RS   68        // smem row stride in floats (17 float4 units, odd -> conflict-dodging)

// ---------------- scratch (static __device__ globals; no allocs) ----------------
__device__ float g_agg1[(size_t)NN * DIMD];
__device__ float g_h1  [(size_t)NN * DIMD];
__device__ float g_bn1 [(size_t)NN * DIMD];
__device__ float g_agg2[(size_t)NN * DIMD];
__device__ float g_h2  [(size_t)NN * FOUT];

__device__ float g_sum1[DIMD], g_sq1[DIMD];
__device__ float g_sum2[FOUT], g_sq2[FOUT];
__device__ float g_a1[DIMD], g_c1[DIMD];
__device__ float g_a2[FOUT], g_c2[FOUT];
__device__ int   g_is64;

// ---------------- init: zero stats + detect index dtype (parallel) ----------------
__global__ void k_init(const unsigned long long* idx) {
    __shared__ int ok;
    int t = threadIdx.x;
    if (t == 0) ok = 1;
    if (t < DIMD) { g_sum1[t] = 0.f; g_sq1[t] = 0.f; }
    if (t < FOUT) { g_sum2[t] = 0.f; g_sq2[t] = 0.f; }
    __syncthreads();
    // int64 indices: every u64 word < 100000. int32 data reinterpreted as u64
    // almost surely produces a huge value somewhere in 64 samples.
    if (t < 64 && idx[t] >= 100000ULL) ok = 0;
    __syncthreads();
    if (t == 0) g_is64 = ok;
}

// ---------------- copy x -> agg1 (identity term of GIN) ----------------
__global__ void k_copy(const float4* __restrict__ src, float4* __restrict__ dst, int n4) {
    int i = blockIdx.x * blockDim.x + threadIdx.x;
    if (i < n4) dst[i] = src[i];
}

// ---------------- edge scatter: agg[dst] += feat[src], float4 atomics ----------------
__global__ void k_scatter(const void* __restrict__ idxbuf,
                          const float4* __restrict__ feat,
                          float4* __restrict__ agg) {
    int g = blockIdx.x * 256 + threadIdx.x;
    int e = g >> 4;
    int f = g & 15;
    int s, d;
    if (g_is64) {
        const long long* p = (const long long*)idxbuf;
        s = (int)p[e]; d = (int)p[(size_t)EE + e];
    } else {
        const int* p = (const int*)idxbuf;
        s = p[e]; d = p[EE + e];
    }
    float4 v = feat[(size_t)s * 16 + f];
    atomicAdd(&agg[(size_t)d * 16 + f], v);
}

// =======================================================================
// Tiled MLP 64->64->64 (ReLU after each Linear).
// Block 256 threads computes a 128x64 tile. Thread (c = tid&15, r = tid>>4)
// owns rows {r+16i} i<8, cols {c+16j} j<4 -> 8x4 register accumulators.
// Hidden activations are written back into the x tile between layers.
// dynamic smem: sX(128*RS) | sWa(64*RS) | sWb(64*RS) | sBa(64) | sBb(64)
// =======================================================================
__global__ __launch_bounds__(256)
void k_mlp64(const float* __restrict__ Wa, const float* __restrict__ ba,
             const float* __restrict__ Wb, const float* __restrict__ bb,
             const float* __restrict__ in, float* __restrict__ out) {
    extern __shared__ float sm[];
    float* sX  = sm;
    float* sWa = sm + 128 * RS;
    float* sWb = sWa + 64 * RS;
    float* sBa = sWb + 64 * RS;
    float* sBb = sBa + 64;

    int tid = threadIdx.x;

    // weights transposed: sW[j*RS + k] = W[k*64 + j]
    for (int i = tid; i < 4096; i += 256) {
        int j = i >> 6, k = i & 63;
        sWa[j * RS + k] = Wa[k * 64 + j];
        sWb[j * RS + k] = Wb[k * 64 + j];
    }
    if (tid < 64) { sBa[tid] = ba[tid]; sBb[tid] = bb[tid]; }

    // x tile: 128 rows x 16 float4
    int row0 = blockIdx.x * 128;
    for (int idx = tid; idx < 2048; idx += 256) {
        int row = idx >> 4, k4 = idx & 15;
        int gr = row0 + row;
        float4 v = make_float4(0.f, 0.f, 0.f, 0.f);
        if (gr < NN) v = ((const float4*)in)[(size_t)gr * 16 + k4];
        *(float4*)&sX[row * RS + k4 * 4] = v;
    }
    __syncthreads();

    int c = tid & 15, r = tid >> 4;

    float acc[8][4];
    #pragma unroll
    for (int i = 0; i < 8; i++)
        #pragma unroll
        for (int j = 0; j < 4; j++) acc[i][j] = sBa[c + 16 * j];

    // ---- layer 1 ----
    #pragma unroll
    for (int k4 = 0; k4 < 16; k4++) {
        float4 xv[8], wv[4];
        #pragma unroll
        for (int i = 0; i < 8; i++) xv[i] = *(const float4*)&sX[(r + 16 * i) * RS + 4 * k4];
        #pragma unroll
        for (int j = 0; j < 4; j++) wv[j] = *(const float4*)&sWa[(c + 16 * j) * RS + 4 * k4];
        #pragma unroll
        for (int i = 0; i < 8; i++)
            #pragma unroll
            for (int j = 0; j < 4; j++) {
                acc[i][j] = fmaf(xv[i].x, wv[j].x, acc[i][j]);
                acc[i][j] = fmaf(xv[i].y, wv[j].y, acc[i][j]);
                acc[i][j] = fmaf(xv[i].z, wv[j].z, acc[i][j]);
                acc[i][j] = fmaf(xv[i].w, wv[j].w, acc[i][j]);
            }
    }
    __syncthreads();

    // ReLU + write hidden back into sX
    #pragma unroll
    for (int i = 0; i < 8; i++)
        #pragma unroll
        for (int j = 0; j < 4; j++)
            sX[(r + 16 * i) * RS + (c + 16 * j)] = fmaxf(acc[i][j], 0.f);
    __syncthreads();

    // ---- layer 2 ----
    #pragma unroll
    for (int i = 0; i < 8; i++)
        #pragma unroll
        for (int j = 0; j < 4; j++) acc[i][j] = sBb[c + 16 * j];

    #pragma unroll
    for (int k4 = 0; k4 < 16; k4++) {
        float4 xv[8], wv[4];
        #pragma unroll
        for (int i = 0; i < 8; i++) xv[i] = *(const float4*)&sX[(r + 16 * i) * RS + 4 * k4];
        #pragma unroll
        for (int j = 0; j < 4; j++) wv[j] = *(const float4*)&sWb[(c + 16 * j) * RS + 4 * k4];
        #pragma unroll
        for (int i = 0; i < 8; i++)
            #pragma unroll
            for (int j = 0; j < 4; j++) {
                acc[i][j] = fmaf(xv[i].x, wv[j].x, acc[i][j]);
                acc[i][j] = fmaf(xv[i].y, wv[j].y, acc[i][j]);
                acc[i][j] = fmaf(xv[i].z, wv[j].z, acc[i][j]);
                acc[i][j] = fmaf(xv[i].w, wv[j].w, acc[i][j]);
            }
    }

    // ReLU + store
    #pragma unroll
    for (int i = 0; i < 8; i++) {
        int gr = row0 + r + 16 * i;
        if (gr < NN) {
            #pragma unroll
            for (int j = 0; j < 4; j++)
                out[(size_t)gr * 64 + c + 16 * j] = fmaxf(acc[i][j], 0.f);
        }
    }
}

// =======================================================================
// Tiled MLP 64->64->2 (ReLU after each Linear).
// Layer 1 identical to k_mlp64; layer 2: 128x2 outputs, one per thread.
// dynamic smem: sX(128*RS) | sWa(64*RS) | sWb(2*RS) | sBa(64) | sBb(2..pad)
// =======================================================================
__global__ __launch_bounds__(256)
void k_mlp2(const float* __restrict__ Wa, const float* __restrict__ ba,
            const float* __restrict__ Wb, const float* __restrict__ bb,
            const float* __restrict__ in, float* __restrict__ out) {
    extern __shared__ float sm[];
    float* sX  = sm;
    float* sWa = sm + 128 * RS;
    float* sWb = sWa + 64 * RS;   // 2 rows of RS
    float* sBa = sWb + 2 * RS;
    float* sBb = sBa + 64;

    int tid = threadIdx.x;

    for (int i = tid; i < 4096; i += 256) {
        int j = i >> 6, k = i & 63;
        sWa[j * RS + k] = Wa[k * 64 + j];
    }
    if (tid < 128) { int j = tid >> 6, k = tid & 63; sWb[j * RS + k] = Wb[k * 2 + j]; }
    if (tid < 64)  sBa[tid] = ba[tid];
    if (tid < 2)   sBb[tid] = bb[tid];

    int row0 = blockIdx.x * 128;
    for (int idx = tid; idx < 2048; idx += 256) {
        int row = idx >> 4, k4 = idx & 15;
        int gr = row0 + row;
        float4 v = make_float4(0.f, 0.f, 0.f, 0.f);
        if (gr < NN) v = ((const float4*)in)[(size_t)gr * 16 + k4];
        *(float4*)&sX[row * RS + k4 * 4] = v;
    }
    __syncthreads();

    int c = tid & 15, r = tid >> 4;

    float acc[8][4];
    #pragma unroll
    for (int i = 0; i < 8; i++)
        #pragma unroll
        for (int j = 0; j < 4; j++) acc[i][j] = sBa[c + 16 * j];

    #pragma unroll
    for (int k4 = 0; k4 < 16; k4++) {
        float4 xv[8], wv[4];
        #pragma unroll
        for (int i = 0; i < 8; i++) xv[i] = *(const float4*)&sX[(r + 16 * i) * RS + 4 * k4];
        #pragma unroll
        for (int j = 0; j < 4; j++) wv[j] = *(const float4*)&sWa[(c + 16 * j) * RS + 4 * k4];
        #pragma unroll
        for (int i = 0; i < 8; i++)
            #pragma unroll
            for (int j = 0; j < 4; j++) {
                acc[i][j] = fmaf(xv[i].x, wv[j].x, acc[i][j]);
                acc[i][j] = fmaf(xv[i].y, wv[j].y, acc[i][j]);
                acc[i][j] = fmaf(xv[i].z, wv[j].z, acc[i][j]);
                acc[i][j] = fmaf(xv[i].w, wv[j].w, acc[i][j]);
            }
    }
    __syncthreads();

    #pragma unroll
    for (int i = 0; i < 8; i++)
        #pragma unroll
        for (int j = 0; j < 4; j++)
            sX[(r + 16 * i) * RS + (c + 16 * j)] = fmaxf(acc[i][j], 0.f);
    __syncthreads();

    // layer 2: one output per thread (128 rows x 2 cols)
    {
        int orow = tid >> 1, col = tid & 1;
        float s0 = sBb[col], s1 = 0.f, s2 = 0.f, s3 = 0.f;
        const float4* hr = (const float4*)&sX[orow * RS];
        const float4* wr = (const float4*)&sWb[col * RS];
        #pragma unroll
        for (int k4 = 0; k4 < 16; k4 += 4) {
            float4 h0 = hr[k4+0], h1 = hr[k4+1], h2 = hr[k4+2], h3 = hr[k4+3];
            float4 w0 = wr[k4+0], w1 = wr[k4+1], w2 = wr[k4+2], w3 = wr[k4+3];
            s0 = fmaf(h0.x, w0.x, s0); s0 = fmaf(h0.y, w0.y, s0);
            s0 = fmaf(h0.z, w0.z, s0); s0 = fmaf(h0.w, w0.w, s0);
            s1 = fmaf(h1.x, w1.x, s1); s1 = fmaf(h1.y, w1.y, s1);
            s1 = fmaf(h1.z, w1.z, s1); s1 = fmaf(h1.w, w1.w, s1);
            s2 = fmaf(h2.x, w2.x, s2); s2 = fmaf(h2.y, w2.y, s2);
            s2 = fmaf(h2.z, w2.z, s2); s2 = fmaf(h2.w, w2.w, s2);
            s3 = fmaf(h3.x, w3.x, s3); s3 = fmaf(h3.y, w3.y, s3);
            s3 = fmaf(h3.z, w3.z, s3); s3 = fmaf(h3.w, w3.w, s3);
        }
        int gr = row0 + orow;
        if (gr < NN) out[(size_t)gr * 2 + col] = fmaxf((s0 + s1) + (s2 + s3), 0.f);
    }
}

// ---------------- column stats: 64 features ----------------
__global__ void k_stats64(const float* __restrict__ h) {
    int tid = threadIdx.x;                       // 256
    size_t gid = (size_t)blockIdx.x * 256 + tid;
    size_t stride = (size_t)gridDim.x * 256;     // multiple of 64
    float s = 0.f, q = 0.f;
    for (size_t i = gid; i < (size_t)NN * 64; i += stride) {
        float v = h[i]; s += v; q += v * v;
    }
    __shared__ float ss[256], sq[256];
    ss[tid] = s; sq[tid] = q;
    __syncthreads();
    if (tid < 64) {
        float S = ss[tid] + ss[tid+64] + ss[tid+128] + ss[tid+192];
        float Q = sq[tid] + sq[tid+64] + sq[tid+128] + sq[tid+192];
        atomicAdd(&g_sum1[tid], S);
        atomicAdd(&g_sq1[tid],  Q);
    }
}

// ---------------- column stats: 2 features ----------------
__global__ void k_stats2(const float* __restrict__ h) {
    int tid = threadIdx.x;                       // 256
    size_t gid = (size_t)blockIdx.x * 256 + tid;
    size_t stride = (size_t)gridDim.x * 256;     // multiple of 2
    float s = 0.f, q = 0.f;
    for (size_t i = gid; i < (size_t)NN * 2; i += stride) {
        float v = h[i]; s += v; q += v * v;
    }
    __shared__ float ss[256], sq[256];
    ss[tid] = s; sq[tid] = q;
    __syncthreads();
    if (tid < 2) {
        float S = 0.f, Q = 0.f;
        for (int i = tid; i < 256; i += 2) { S += ss[i]; Q += sq[i]; }
        atomicAdd(&g_sum2[tid], S);
        atomicAdd(&g_sq2[tid],  Q);
    }
}

// ---------------- finalize BN affine ----------------
__global__ void k_finalize(const float* __restrict__ sum, const float* __restrict__ sq,
                           const float* __restrict__ g, const float* __restrict__ be,
                           float* __restrict__ a, float* __restrict__ c, int n) {
    int i = threadIdx.x;
    if (i < n) {
        float mu  = sum[i] * (1.f / NN);
        float var = sq[i] * (1.f / NN) - mu * mu;
        float rs  = rsqrtf(var + BN_EPS);
        float aa  = g[i] * rs;
        a[i] = aa;
        c[i] = be[i] - mu * aa;
    }
}

// ---------------- apply BN1 and seed agg2 ----------------
__global__ void k_apply1(const float4* __restrict__ h,
                         float4* __restrict__ bn, float4* __restrict__ agg) {
    __shared__ float sa[64], sc[64];
    if (threadIdx.x < 64) { sa[threadIdx.x] = g_a1[threadIdx.x]; sc[threadIdx.x] = g_c1[threadIdx.x]; }
    __syncthreads();
    int i = blockIdx.x * blockDim.x + threadIdx.x;
    if (i < NN * 16) {
        int f = (i & 15) * 4;
        float4 v = h[i];
        v.x = v.x * sa[f+0] + sc[f+0];
        v.y = v.y * sa[f+1] + sc[f+1];
        v.z = v.z * sa[f+2] + sc[f+2];
        v.w = v.w * sa[f+3] + sc[f+3];
        bn[i]  = v;
        agg[i] = v;
    }
}

// ---------------- apply BN2 -> d_out ----------------
__global__ void k_apply2(const float2* __restrict__ h, float2* __restrict__ out) {
    int i = blockIdx.x * blockDim.x + threadIdx.x;
    if (i < NN) {
        float a0 = g_a2[0], a1 = g_a2[1], c0 = g_c2[0], c1 = g_c2[1];
        float2 v = h[i];
        out[i] = make_float2(v.x * a0 + c0, v.y * a1 + c1);
    }
}

// ---------------- launch ----------------
extern "C" void kernel_launch(void* const* d_in, const int* in_sizes, int n_in,
                              void* d_out, int out_size) {
    const float* x    = (const float*)d_in[0];
    const void*  eidx = d_in[1];
    const float* W1a  = (const float*)d_in[2];
    const float* b1a  = (const float*)d_in[3];
    const float* W1b  = (const float*)d_in[4];
    const float* b1b  = (const float*)d_in[5];
    const float* g1   = (const float*)d_in[6];
    const float* be1  = (const float*)d_in[7];
    const float* W5a  = (const float*)d_in[8];
    const float* b5a  = (const float*)d_in[9];
    const float* W5b  = (const float*)d_in[10];
    const float* b5b  = (const float*)d_in[11];
    const float* g5   = (const float*)d_in[12];
    const float* be5  = (const float*)d_in[13];

    float *agg1, *h1, *bn1, *agg2, *h2;
    float *sum1, *sq1, *sum2, *sq2, *a1, *c1, *a2, *c2;
    cudaGetSymbolAddress((void**)&agg1, g_agg1);
    cudaGetSymbolAddress((void**)&h1,   g_h1);
    cudaGetSymbolAddress((void**)&bn1,  g_bn1);
    cudaGetSymbolAddress((void**)&agg2, g_agg2);
    cudaGetSymbolAddress((void**)&h2,   g_h2);
    cudaGetSymbolAddress((void**)&sum1, g_sum1);
    cudaGetSymbolAddress((void**)&sq1,  g_sq1);
    cudaGetSymbolAddress((void**)&sum2, g_sum2);
    cudaGetSymbolAddress((void**)&sq2,  g_sq2);
    cudaGetSymbolAddress((void**)&a1,   g_a1);
    cudaGetSymbolAddress((void**)&c1,   g_c1);
    cudaGetSymbolAddress((void**)&a2,   g_a2);
    cudaGetSymbolAddress((void**)&c2,   g_c2);

    const int smem_mlp64 = (128 * RS + 64 * RS + 64 * RS + 128) * 4;
    const int smem_mlp2  = (128 * RS + 64 * RS + 2 * RS + 80) * 4;
    cudaFuncSetAttribute(k_mlp64, cudaFuncAttributeMaxDynamicSharedMemorySize, smem_mlp64);
    cudaFuncSetAttribute(k_mlp2,  cudaFuncAttributeMaxDynamicSharedMemorySize, smem_mlp2);

    const int nb_copy    = (NN * 16 + 255) / 256;
    const int nb_scatter = (EE * 16) / 256;           // exact
    const int nb_mlp     = (NN + 127) / 128;
    const int nb_apply2  = (NN + 255) / 256;

    // layer 1
    k_init<<<1, 128>>>((const unsigned long long*)eidx);
    k_copy<<<nb_copy, 256>>>((const float4*)x, (float4*)agg1, NN * 16);
    k_scatter<<<nb_scatter, 256>>>(eidx, (const float4*)x, (float4*)agg1);
    k_mlp64<<<nb_mlp, 256, smem_mlp64>>>(W1a, b1a, W1b, b1b, agg1, h1);
    k_stats64<<<256, 256>>>(h1);
    k_finalize<<<1, 64>>>(sum1, sq1, g1, be1, a1, c1, DIMD);
    k_apply1<<<nb_copy, 256>>>((const float4*)h1, (float4*)bn1, (float4*)agg2);
    // layer 2
    k_scatter<<<nb_scatter, 256>>>(eidx, (const float4*)bn1, (float4*)agg2);
    k_mlp2<<<nb_mlp, 256, smem_mlp2>>>(W5a, b5a, W5b, b5b, agg2, h2);
    k_stats2<<<128, 256>>>(h2);
    k_finalize<<<1, 64>>>(sum2, sq2, g5, be5, a2, c2, FOUT);
    k_apply2<<<nb_apply2, 256>>>((const float2*)h2, (float2*)d_out);
}

// round 3
// speedup vs baseline: 1.5412x; 1.3237x over previous
#include <cuda_runtime.h>

#define NN   100000
#define EE   1600000
#define DIMD 64
#define FOUT 2
#define BN_EPS 1e-5f
#define RS   68        // smem row stride in floats

// ---------------- scratch (static __device__ globals; no allocs) ----------------
__device__ float g_agg1[(size_t)NN * DIMD];
__device__ float g_h1  [(size_t)NN * DIMD];
__device__ float g_agg2[(size_t)NN * DIMD];
__device__ float g_h2  [(size_t)NN * FOUT];

__device__ int g_deg[NN];
__device__ int g_rowptr[NN + 1];
__device__ int g_pos[NN];
__device__ int g_srcs[EE];
__device__ int g_bsum[512];

__device__ float g_sum1[DIMD], g_sq1[DIMD];
__device__ float g_sum2[FOUT], g_sq2[FOUT];
__device__ float g_a1[DIMD], g_c1[DIMD];
__device__ float g_a2[FOUT], g_c2[FOUT];
__device__ int   g_is64;

// ---------------- init: zero stats + detect index dtype ----------------
__global__ void k_init(const unsigned long long* idx) {
    __shared__ int ok;
    int t = threadIdx.x;
    if (t == 0) ok = 1;
    if (t < DIMD) { g_sum1[t] = 0.f; g_sq1[t] = 0.f; }
    if (t < FOUT) { g_sum2[t] = 0.f; g_sq2[t] = 0.f; }
    __syncthreads();
    if (t < 64 && idx[t] >= 100000ULL) ok = 0;
    __syncthreads();
    if (t == 0) g_is64 = ok;
}

__global__ void k_zerodeg() {
    int i = blockIdx.x * 256 + threadIdx.x;
    if (i < NN) g_deg[i] = 0;
}

// ---------------- histogram of dst ----------------
__global__ void k_hist(const void* __restrict__ idxbuf) {
    int e = blockIdx.x * 256 + threadIdx.x;   // grid exactly EE/256
    int d;
    if (g_is64) d = (int)((const long long*)idxbuf)[(size_t)EE + e];
    else        d = ((const int*)idxbuf)[EE + e];
    atomicAdd(&g_deg[d], 1);
}

// ---------------- 3-kernel exclusive scan over deg -> rowptr ----------------
__global__ void k_scan1() {                    // 391 blocks x 256
    __shared__ int sd[256];
    int t = threadIdx.x;
    int i = blockIdx.x * 256 + t;
    int v = (i < NN) ? g_deg[i] : 0;
    sd[t] = v;
    __syncthreads();
    #pragma unroll
    for (int off = 1; off < 256; off <<= 1) {
        int u = (t >= off) ? sd[t - off] : 0;
        __syncthreads();
        sd[t] += u;
        __syncthreads();
    }
    if (i < NN) g_rowptr[i] = sd[t] - v;       // exclusive within block
    if (t == 255) g_bsum[blockIdx.x] = sd[255];
}

__global__ void k_scan2() {                    // 1 block x 512
    __shared__ int sd[512];
    int t = threadIdx.x;
    int v = (t < 391) ? g_bsum[t] : 0;
    sd[t] = v;
    __syncthreads();
    #pragma unroll
    for (int off = 1; off < 512; off <<= 1) {
        int u = (t >= off) ? sd[t - off] : 0;
        __syncthreads();
        sd[t] += u;
        __syncthreads();
    }
    if (t < 391) g_bsum[t] = sd[t] - v;        // exclusive block offsets
}

__global__ void k_scan3() {                    // 391 blocks x 256
    int i = blockIdx.x * 256 + threadIdx.x;
    if (i < NN) {
        int r = g_rowptr[i] + g_bsum[blockIdx.x];
        g_rowptr[i] = r;
        g_pos[i] = r;
    }
    if (i == 0) g_rowptr[NN] = EE;
}

// ---------------- fill CSR src list ----------------
__global__ void k_fill(const void* __restrict__ idxbuf) {
    int e = blockIdx.x * 256 + threadIdx.x;
    int s, d;
    if (g_is64) {
        const long long* p = (const long long*)idxbuf;
        s = (int)p[e]; d = (int)p[(size_t)EE + e];
    } else {
        const int* p = (const int*)idxbuf;
        s = p[e]; d = p[EE + e];
    }
    int p = atomicAdd(&g_pos[d], 1);
    g_srcs[p] = s;
}

// ---------------- CSR aggregation: agg[i] = x[i] + sum x[src] ----------------
// one warp per node; lane holds float2 (2 features)
__global__ __launch_bounds__(256)
void k_agg1(const float2* __restrict__ x, float2* __restrict__ agg) {
    int w = (blockIdx.x * 256 + threadIdx.x) >> 5;
    int lane = threadIdx.x & 31;
    if (w >= NN) return;
    int beg = g_rowptr[w], end = g_rowptr[w + 1];

    float2 a0 = x[(size_t)w * 32 + lane];
    float2 a1 = make_float2(0.f, 0.f);

    int base = beg;
    for (; base + 4 <= end; base += 4) {
        int sl = (lane < 4) ? g_srcs[base + lane] : 0;
        int s0 = __shfl_sync(0xffffffffu, sl, 0);
        int s1 = __shfl_sync(0xffffffffu, sl, 1);
        int s2 = __shfl_sync(0xffffffffu, sl, 2);
        int s3 = __shfl_sync(0xffffffffu, sl, 3);
        float2 v0 = x[(size_t)s0 * 32 + lane];
        float2 v1 = x[(size_t)s1 * 32 + lane];
        float2 v2 = x[(size_t)s2 * 32 + lane];
        float2 v3 = x[(size_t)s3 * 32 + lane];
        a0.x += v0.x; a0.y += v0.y;
        a1.x += v1.x; a1.y += v1.y;
        a0.x += v2.x; a0.y += v2.y;
        a1.x += v3.x; a1.y += v3.y;
    }
    for (; base < end; base++) {
        int sl = (lane == 0) ? g_srcs[base] : 0;
        int s = __shfl_sync(0xffffffffu, sl, 0);
        float2 v = x[(size_t)s * 32 + lane];
        a0.x += v.x; a0.y += v.y;
    }
    agg[(size_t)w * 32 + lane] = make_float2(a0.x + a1.x, a0.y + a1.y);
}

// ---------------- CSR aggregation with BN1 folded in ----------------
// agg2[i] = a1 (x) (h[i] + sum h[src]) + (1+deg_i) * c1
__global__ __launch_bounds__(256)
void k_agg2(const float2* __restrict__ h, float2* __restrict__ agg) {
    int w = (blockIdx.x * 256 + threadIdx.x) >> 5;
    int lane = threadIdx.x & 31;
    if (w >= NN) return;
    int beg = g_rowptr[w], end = g_rowptr[w + 1];

    float2 a0 = h[(size_t)w * 32 + lane];
    float2 a1 = make_float2(0.f, 0.f);

    int base = beg;
    for (; base + 4 <= end; base += 4) {
        int sl = (lane < 4) ? g_srcs[base + lane] : 0;
        int s0 = __shfl_sync(0xffffffffu, sl, 0);
        int s1 = __shfl_sync(0xffffffffu, sl, 1);
        int s2 = __shfl_sync(0xffffffffu, sl, 2);
        int s3 = __shfl_sync(0xffffffffu, sl, 3);
        float2 v0 = h[(size_t)s0 * 32 + lane];
        float2 v1 = h[(size_t)s1 * 32 + lane];
        float2 v2 = h[(size_t)s2 * 32 + lane];
        float2 v3 = h[(size_t)s3 * 32 + lane];
        a0.x += v0.x; a0.y += v0.y;
        a1.x += v1.x; a1.y += v1.y;
        a0.x += v2.x; a0.y += v2.y;
        a1.x += v3.x; a1.y += v3.y;
    }
    for (; base < end; base++) {
        int sl = (lane == 0) ? g_srcs[base] : 0;
        int s = __shfl_sync(0xffffffffu, sl, 0);
        float2 v = h[(size_t)s * 32 + lane];
        a0.x += v.x; a0.y += v.y;
    }
    float sx = a0.x + a1.x, sy = a0.y + a1.y;
    float scale = (float)(1 + (end - beg));
    float aa0 = g_a1[2 * lane], aa1 = g_a1[2 * lane + 1];
    float cc0 = g_c1[2 * lane], cc1 = g_c1[2 * lane + 1];
    agg[(size_t)w * 32 + lane] = make_float2(sx * aa0 + scale * cc0,
                                             sy * aa1 + scale * cc1);
}

// =======================================================================
// Tiled MLP 64->64->64 (ReLU after each Linear). 256 thr, 128x64 tile.
// =======================================================================
__global__ __launch_bounds__(256)
void k_mlp64(const float* __restrict__ Wa, const float* __restrict__ ba,
             const float* __restrict__ Wb, const float* __restrict__ bb,
             const float* __restrict__ in, float* __restrict__ out) {
    extern __shared__ float sm[];
    float* sX  = sm;
    float* sWa = sm + 128 * RS;
    float* sWb = sWa + 64 * RS;
    float* sBa = sWb + 64 * RS;
    float* sBb = sBa + 64;

    int tid = threadIdx.x;

    for (int i = tid; i < 4096; i += 256) {
        int j = i >> 6, k = i & 63;
        sWa[j * RS + k] = Wa[k * 64 + j];
        sWb[j * RS + k] = Wb[k * 64 + j];
    }
    if (tid < 64) { sBa[tid] = ba[tid]; sBb[tid] = bb[tid]; }

    int row0 = blockIdx.x * 128;
    for (int idx = tid; idx < 2048; idx += 256) {
        int row = idx >> 4, k4 = idx & 15;
        int gr = row0 + row;
        float4 v = make_float4(0.f, 0.f, 0.f, 0.f);
        if (gr < NN) v = ((const float4*)in)[(size_t)gr * 16 + k4];
        *(float4*)&sX[row * RS + k4 * 4] = v;
    }
    __syncthreads();

    int c = tid & 15, r = tid >> 4;

    float acc[8][4];
    #pragma unroll
    for (int i = 0; i < 8; i++)
        #pragma unroll
        for (int j = 0; j < 4; j++) acc[i][j] = sBa[c + 16 * j];

    #pragma unroll
    for (int k4 = 0; k4 < 16; k4++) {
        float4 xv[8], wv[4];
        #pragma unroll
        for (int i = 0; i < 8; i++) xv[i] = *(const float4*)&sX[(r + 16 * i) * RS + 4 * k4];
        #pragma unroll
        for (int j = 0; j < 4; j++) wv[j] = *(const float4*)&sWa[(c + 16 * j) * RS + 4 * k4];
        #pragma unroll
        for (int i = 0; i < 8; i++)
            #pragma unroll
            for (int j = 0; j < 4; j++) {
                acc[i][j] = fmaf(xv[i].x, wv[j].x, acc[i][j]);
                acc[i][j] = fmaf(xv[i].y, wv[j].y, acc[i][j]);
                acc[i][j] = fmaf(xv[i].z, wv[j].z, acc[i][j]);
                acc[i][j] = fmaf(xv[i].w, wv[j].w, acc[i][j]);
            }
    }
    __syncthreads();

    #pragma unroll
    for (int i = 0; i < 8; i++)
        #pragma unroll
        for (int j = 0; j < 4; j++)
            sX[(r + 16 * i) * RS + (c + 16 * j)] = fmaxf(acc[i][j], 0.f);
    __syncthreads();

    #pragma unroll
    for (int i = 0; i < 8; i++)
        #pragma unroll
        for (int j = 0; j < 4; j++) acc[i][j] = sBb[c + 16 * j];

    #pragma unroll
    for (int k4 = 0; k4 < 16; k4++) {
        float4 xv[8], wv[4];
        #pragma unroll
        for (int i = 0; i < 8; i++) xv[i] = *(const float4*)&sX[(r + 16 * i) * RS + 4 * k4];
        #pragma unroll
        for (int j = 0; j < 4; j++) wv[j] = *(const float4*)&sWb[(c + 16 * j) * RS + 4 * k4];
        #pragma unroll
        for (int i = 0; i < 8; i++)
            #pragma unroll
            for (int j = 0; j < 4; j++) {
                acc[i][j] = fmaf(xv[i].x, wv[j].x, acc[i][j]);
                acc[i][j] = fmaf(xv[i].y, wv[j].y, acc[i][j]);
                acc[i][j] = fmaf(xv[i].z, wv[j].z, acc[i][j]);
                acc[i][j] = fmaf(xv[i].w, wv[j].w, acc[i][j]);
            }
    }

    #pragma unroll
    for (int i = 0; i < 8; i++) {
        int gr = row0 + r + 16 * i;
        if (gr < NN) {
            #pragma unroll
            for (int j = 0; j < 4; j++)
                out[(size_t)gr * 64 + c + 16 * j] = fmaxf(acc[i][j], 0.f);
        }
    }
}

// =======================================================================
// Tiled MLP 64->64->2 (ReLU after each Linear).
// =======================================================================
__global__ __launch_bounds__(256)
void k_mlp2(const float* __restrict__ Wa, const float* __restrict__ ba,
            const float* __restrict__ Wb, const float* __restrict__ bb,
            const float* __restrict__ in, float* __restrict__ out) {
    extern __shared__ float sm[];
    float* sX  = sm;
    float* sWa = sm + 128 * RS;
    float* sWb = sWa + 64 * RS;
    float* sBa = sWb + 2 * RS;
    float* sBb = sBa + 64;

    int tid = threadIdx.x;

    for (int i = tid; i < 4096; i += 256) {
        int j = i >> 6, k = i & 63;
        sWa[j * RS + k] = Wa[k * 64 + j];
    }
    if (tid < 128) { int j = tid >> 6, k = tid & 63; sWb[j * RS + k] = Wb[k * 2 + j]; }
    if (tid < 64)  sBa[tid] = ba[tid];
    if (tid < 2)   sBb[tid] = bb[tid];

    int row0 = blockIdx.x * 128;
    for (int idx = tid; idx < 2048; idx += 256) {
        int row = idx >> 4, k4 = idx & 15;
        int gr = row0 + row;
        float4 v = make_float4(0.f, 0.f, 0.f, 0.f);
        if (gr < NN) v = ((const float4*)in)[(size_t)gr * 16 + k4];
        *(float4*)&sX[row * RS + k4 * 4] = v;
    }
    __syncthreads();

    int c = tid & 15, r = tid >> 4;

    float acc[8][4];
    #pragma unroll
    for (int i = 0; i < 8; i++)
        #pragma unroll
        for (int j = 0; j < 4; j++) acc[i][j] = sBa[c + 16 * j];

    #pragma unroll
    for (int k4 = 0; k4 < 16; k4++) {
        float4 xv[8], wv[4];
        #pragma unroll
        for (int i = 0; i < 8; i++) xv[i] = *(const float4*)&sX[(r + 16 * i) * RS + 4 * k4];
        #pragma unroll
        for (int j = 0; j < 4; j++) wv[j] = *(const float4*)&sWa[(c + 16 * j) * RS + 4 * k4];
        #pragma unroll
        for (int i = 0; i < 8; i++)
            #pragma unroll
            for (int j = 0; j < 4; j++) {
                acc[i][j] = fmaf(xv[i].x, wv[j].x, acc[i][j]);
                acc[i][j] = fmaf(xv[i].y, wv[j].y, acc[i][j]);
                acc[i][j] = fmaf(xv[i].z, wv[j].z, acc[i][j]);
                acc[i][j] = fmaf(xv[i].w, wv[j].w, acc[i][j]);
            }
    }
    __syncthreads();

    #pragma unroll
    for (int i = 0; i < 8; i++)
        #pragma unroll
        for (int j = 0; j < 4; j++)
            sX[(r + 16 * i) * RS + (c + 16 * j)] = fmaxf(acc[i][j], 0.f);
    __syncthreads();

    {
        int orow = tid >> 1, col = tid & 1;
        float s0 = sBb[col], s1 = 0.f, s2 = 0.f, s3 = 0.f;
        const float4* hr = (const float4*)&sX[orow * RS];
        const float4* wr = (const float4*)&sWb[col * RS];
        #pragma unroll
        for (int k4 = 0; k4 < 16; k4 += 4) {
            float4 h0 = hr[k4+0], h1 = hr[k4+1], h2 = hr[k4+2], h3 = hr[k4+3];
            float4 w0 = wr[k4+0], w1 = wr[k4+1], w2 = wr[k4+2], w3 = wr[k4+3];
            s0 = fmaf(h0.x, w0.x, s0); s0 = fmaf(h0.y, w0.y, s0);
            s0 = fmaf(h0.z, w0.z, s0); s0 = fmaf(h0.w, w0.w, s0);
            s1 = fmaf(h1.x, w1.x, s1); s1 = fmaf(h1.y, w1.y, s1);
            s1 = fmaf(h1.z, w1.z, s1); s1 = fmaf(h1.w, w1.w, s1);
            s2 = fmaf(h2.x, w2.x, s2); s2 = fmaf(h2.y, w2.y, s2);
            s2 = fmaf(h2.z, w2.z, s2); s2 = fmaf(h2.w, w2.w, s2);
            s3 = fmaf(h3.x, w3.x, s3); s3 = fmaf(h3.y, w3.y, s3);
            s3 = fmaf(h3.z, w3.z, s3); s3 = fmaf(h3.w, w3.w, s3);
        }
        int gr = row0 + orow;
        if (gr < NN) out[(size_t)gr * 2 + col] = fmaxf((s0 + s1) + (s2 + s3), 0.f);
    }
}

// ---------------- column stats ----------------
__global__ void k_stats64(const float* __restrict__ h) {
    int tid = threadIdx.x;
    size_t gid = (size_t)blockIdx.x * 256 + tid;
    size_t stride = (size_t)gridDim.x * 256;
    float s = 0.f, q = 0.f;
    for (size_t i = gid; i < (size_t)NN * 64; i += stride) {
        float v = h[i]; s += v; q += v * v;
    }
    __shared__ float ss[256], sq[256];
    ss[tid] = s; sq[tid] = q;
    __syncthreads();
    if (tid < 64) {
        float S = ss[tid] + ss[tid+64] + ss[tid+128] + ss[tid+192];
        float Q = sq[tid] + sq[tid+64] + sq[tid+128] + sq[tid+192];
        atomicAdd(&g_sum1[tid], S);
        atomicAdd(&g_sq1[tid],  Q);
    }
}

__global__ void k_stats2(const float* __restrict__ h) {
    int tid = threadIdx.x;
    size_t gid = (size_t)blockIdx.x * 256 + tid;
    size_t stride = (size_t)gridDim.x * 256;
    float s = 0.f, q = 0.f;
    for (size_t i = gid; i < (size_t)NN * 2; i += stride) {
        float v = h[i]; s += v; q += v * v;
    }
    __shared__ float ss[256], sq[256];
    ss[tid] = s; sq[tid] = q;
    __syncthreads();
    if (tid < 2) {
        float S = 0.f, Q = 0.f;
        for (int i = tid; i < 256; i += 2) { S += ss[i]; Q += sq[i]; }
        atomicAdd(&g_sum2[tid], S);
        atomicAdd(&g_sq2[tid],  Q);
    }
}

// ---------------- finalize BN affine ----------------
__global__ void k_finalize(const float* __restrict__ sum, const float* __restrict__ sq,
                           const float* __restrict__ g, const float* __restrict__ be,
                           float* __restrict__ a, float* __restrict__ c, int n) {
    int i = threadIdx.x;
    if (i < n) {
        float mu  = sum[i] * (1.f / NN);
        float var = sq[i] * (1.f / NN) - mu * mu;
        float rs  = rsqrtf(var + BN_EPS);
        float aa  = g[i] * rs;
        a[i] = aa;
        c[i] = be[i] - mu * aa;
    }
}

// ---------------- apply BN2 -> d_out ----------------
__global__ void k_apply2(const float2* __restrict__ h, float2* __restrict__ out) {
    int i = blockIdx.x * blockDim.x + threadIdx.x;
    if (i < NN) {
        float a0 = g_a2[0], a1 = g_a2[1], c0 = g_c2[0], c1 = g_c2[1];
        float2 v = h[i];
        out[i] = make_float2(v.x * a0 + c0, v.y * a1 + c1);
    }
}

// ---------------- launch ----------------
extern "C" void kernel_launch(void* const* d_in, const int* in_sizes, int n_in,
                              void* d_out, int out_size) {
    const float* x    = (const float*)d_in[0];
    const void*  eidx = d_in[1];
    const float* W1a  = (const float*)d_in[2];
    const float* b1a  = (const float*)d_in[3];
    const float* W1b  = (const float*)d_in[4];
    const float* b1b  = (const float*)d_in[5];
    const float* g1   = (const float*)d_in[6];
    const float* be1  = (const float*)d_in[7];
    const float* W5a  = (const float*)d_in[8];
    const float* b5a  = (const float*)d_in[9];
    const float* W5b  = (const float*)d_in[10];
    const float* b5b  = (const float*)d_in[11];
    const float* g5   = (const float*)d_in[12];
    const float* be5  = (const float*)d_in[13];

    float *agg1, *h1, *agg2, *h2;
    float *sum1, *sq1, *sum2, *sq2, *a1, *c1, *a2, *c2;
    cudaGetSymbolAddress((void**)&agg1, g_agg1);
    cudaGetSymbolAddress((void**)&h1,   g_h1);
    cudaGetSymbolAddress((void**)&agg2, g_agg2);
    cudaGetSymbolAddress((void**)&h2,   g_h2);
    cudaGetSymbolAddress((void**)&sum1, g_sum1);
    cudaGetSymbolAddress((void**)&sq1,  g_sq1);
    cudaGetSymbolAddress((void**)&sum2, g_sum2);
    cudaGetSymbolAddress((void**)&sq2,  g_sq2);
    cudaGetSymbolAddress((void**)&a1,   g_a1);
    cudaGetSymbolAddress((void**)&c1,   g_c1);
    cudaGetSymbolAddress((void**)&a2,   g_a2);
    cudaGetSymbolAddress((void**)&c2,   g_c2);

    const int smem_mlp64 = (128 * RS + 64 * RS + 64 * RS + 128) * 4;
    const int smem_mlp2  = (128 * RS + 64 * RS + 2 * RS + 80) * 4;
    cudaFuncSetAttribute(k_mlp64, cudaFuncAttributeMaxDynamicSharedMemorySize, smem_mlp64);
    cudaFuncSetAttribute(k_mlp2,  cudaFuncAttributeMaxDynamicSharedMemorySize, smem_mlp2);

    const int nb_edge = EE / 256;                 // 6250 exact
    const int nb_node = (NN + 255) / 256;         // 391
    const int nb_agg  = (NN * 32 + 255) / 256;    // 12500
    const int nb_mlp  = (NN + 127) / 128;

    // build CSR (shared by both layers)
    k_init<<<1, 128>>>((const unsigned long long*)eidx);
    k_zerodeg<<<nb_node, 256>>>();
    k_hist<<<nb_edge, 256>>>(eidx);
    k_scan1<<<nb_node, 256>>>();
    k_scan2<<<1, 512>>>();
    k_scan3<<<nb_node, 256>>>();
    k_fill<<<nb_edge, 256>>>(eidx);

    // layer 1
    k_agg1<<<nb_agg, 256>>>((const float2*)x, (float2*)agg1);
    k_mlp64<<<nb_mlp, 256, smem_mlp64>>>(W1a, b1a, W1b, b1b, agg1, h1);
    k_stats64<<<256, 256>>>(h1);
    k_finalize<<<1, 64>>>(sum1, sq1, g1, be1, a1, c1, DIMD);
    // layer 2 (BN1 folded into aggregation)
    k_agg2<<<nb_agg, 256>>>((const float2*)h1, (float2*)agg2);
    k_mlp2<<<nb_mlp, 256, smem_mlp2>>>(W5a, b5a, W5b, b5b, agg2, h2);
    k_stats2<<<128, 256>>>(h2);
    k_finalize<<<1, 64>>>(sum2, sq2, g5, be5, a2, c2, FOUT);
    k_apply2<<<nb_node, 256>>>((const float2*)h2, (float2*)d_out);
}